// round 12
// baseline (speedup 1.0000x reference)
#include <cuda_runtime.h>
#include <cuda_fp16.h>
#include <math.h>
#include <stdint.h>

#define HH 256
#define WW 256
#define BB 4
#define CIN 128
#define NOC 128
#define NSTAGE 24                        // (8 cin-chunks of 16) x (3 dy)

#define A_WORDS 3072                     // per-stage A: [3 kc][8 blk][32 lane][4 x fp16x2]
#define X_STRIDE 136                     // uint32 (fp16x2) words per cin-pair row
#define X_WORDS (8 * X_STRIDE)           // 1088
#define BUF_BYTES ((A_WORDS + X_WORDS) * 4)      // 16640
#define AOFF(p) ((p) * BUF_BYTES)
#define XOFF(p) ((p) * BUF_BYTES + A_WORDS * 4)
#define DYN_BYTES (2 * BUF_BYTES)                // 33280

// ---------------- device scratch ----------------
__device__ uint32_t g_wA[NSTAGE * A_WORDS]; // fragment-permuted fp16x2, BN-folded
__device__ float g_bfold[NOC];
__device__ float g_attw[NOC];
__device__ float g_att[2 * BB * HH * WW];

// ---------------- helpers ----------------
__device__ __forceinline__ uint32_t smem_u32(const void* p) {
    uint32_t a;
    asm("{ .reg .u64 t; cvta.to.shared.u64 t, %1; cvt.u32.u64 %0, t; }" : "=r"(a) : "l"(p));
    return a;
}
__device__ __forceinline__ uint32_t packh2(float a, float b) {
    __half2 h = __floats2half2_rn(a, b);
    return *reinterpret_cast<uint32_t*>(&h);
}
__device__ __forceinline__ void cp16(uint32_t dst, const void* src) {
    asm volatile("cp.async.cg.shared.global [%0], [%1], 16;" :: "r"(dst), "l"(src));
}
__device__ __forceinline__ void mma16(float* d, const uint32_t* a, uint32_t b0, uint32_t b1) {
    asm volatile(
        "mma.sync.aligned.m16n8k16.row.col.f32.f16.f16.f32 "
        "{%0,%1,%2,%3},{%4,%5,%6,%7},{%8,%9},{%0,%1,%2,%3};"
        : "+f"(d[0]), "+f"(d[1]), "+f"(d[2]), "+f"(d[3])
        : "r"(a[0]), "r"(a[1]), "r"(a[2]), "r"(a[3]), "r"(b0), "r"(b1));
}

// ---------------- kernel 0: BN fold + fragment-permuted fp16 weight tiles ----------------
// g_wA[s][kc][blk][lane][e]: oc = blk*16 + g + 8*(e&1); pair = tig + 4*(e>>1);
//   cin = (s/3)*16 + 2*pair + {0,1} (packed lo,hi); dy = s%3; dxi = kc.
__global__ void setup_kernel(
    const float* __restrict__ wa, const float* __restrict__ ba,
    const float* __restrict__ wb, const float* __restrict__ bb,
    const float* __restrict__ ga, const float* __restrict__ bta,
    const float* __restrict__ ma, const float* __restrict__ va,
    const float* __restrict__ gb, const float* __restrict__ btb,
    const float* __restrict__ mb, const float* __restrict__ vb,
    const float* __restrict__ attaw, const float* __restrict__ attbw)
{
    int idx = blockIdx.x * blockDim.x + threadIdx.x;
    if (idx < NOC) {
        int oc = idx;
        bool isa = oc < 64;
        int o = isa ? oc : oc - 64;
        float gamma = isa ? ga[o] : gb[o];
        float beta  = isa ? bta[o] : btb[o];
        float mean  = isa ? ma[o] : mb[o];
        float var   = isa ? va[o] : vb[o];
        float A = gamma / sqrtf(var + 1e-3f);
        float bias = isa ? ba[o] : bb[o];
        g_bfold[oc] = (bias - mean) * A + beta;
        g_attw[oc]  = isa ? attaw[o] : attbw[o];
    }
    if (idx < NSTAGE * A_WORDS) {
        int e    = idx & 3;
        int lane = (idx >> 2) & 31;
        int blk  = (idx >> 7) & 7;
        int kc   = (idx >> 10) % 3;
        int s    = idx / A_WORDS;
        int g    = lane >> 2;
        int tig  = lane & 3;
        int oc   = blk * 16 + g + ((e & 1) ? 8 : 0);
        int pair = tig + ((e & 2) ? 4 : 0);
        int cin0 = (s / 3) * 16 + 2 * pair;
        int dy   = s % 3;
        bool isa = oc < 64;
        int o = isa ? oc : oc - 64;
        float gamma = isa ? ga[o] : gb[o];
        float var   = isa ? va[o] : vb[o];
        float A = gamma / sqrtf(var + 1e-3f);
        const float* w = isa ? wa : wb;
        float v0 = w[((o * CIN + cin0)     * 3 + dy) * 3 + kc] * A;
        float v1 = w[((o * CIN + cin0 + 1) * 3 + dy) * 3 + kc] * A;
        g_wA[idx] = packh2(v0, v1);
    }
}

// ---------------- kernel 1: mma.sync fp16-k16 conv + BN + 1x1 attention logit ----------------
// grid (2, 256, 4) = (col half, row y, batch). 512 threads, 16 warps, 2 CTAs/SM.
// warp w: oc0 = (w>>2)*32, pix0 = (w&3)*32. D = 128oc x 128pix, K = 24 stages x 48.
__global__ void __launch_bounds__(512, 2) conv_att_kernel(
    const float* __restrict__ x, float* __restrict__ out,
    const float* __restrict__ attaw, const float* __restrict__ attab,
    const float* __restrict__ attbw, const float* __restrict__ attbb,
    const float* __restrict__ abga, const float* __restrict__ abba,
    const float* __restrict__ abma, const float* __restrict__ abva,
    const float* __restrict__ abgb, const float* __restrict__ abbb,
    const float* __restrict__ abmb, const float* __restrict__ abvb)
{
    extern __shared__ __align__(16) char dyn[];
    const int tid  = threadIdx.x;
    const int b    = blockIdx.z;
    const int y    = blockIdx.y;
    const int c0   = blockIdx.x * 128;
    const int w    = tid >> 5;
    const int lane = tid & 31;
    const int g    = lane >> 2;
    const int tig  = lane & 3;
    const int oc0  = (w >> 2) * 32;
    const int pix0 = (w & 3) * 32;
    const int blk0 = (w >> 2) * 2;
    const uint32_t dynb = smem_u32(dyn);

    float c[2][4][4];
    #pragma unroll
    for (int mm = 0; mm < 2; mm++)
        #pragma unroll
        for (int nn = 0; nn < 4; nn++)
            #pragma unroll
            for (int k = 0; k < 4; k++) c[mm][nn][k] = 0.f;

    const int c2  = tid >> 6;            // cin pair 0..7
    const int l64 = tid & 63;            // col group

    // A stage copy: 768 x 16B chunks
    auto stage_A = [&](int s, int p) {
        const char* src = (const char*)(g_wA + (size_t)s * A_WORDS) + tid * 16;
        cp16(dynb + AOFF(p) + tid * 16, src);
        if (tid < 256) cp16(dynb + AOFF(p) + 8192 + tid * 16, src + 8192);
        asm volatile("cp.async.commit_group;" ::: "memory");
    };
    // X loads for stage s into regs (3 col groups x 2 cin)
    auto load_X = [&](int s, float* v0, float* v1) {
        int grow = y + (s % 3) - 1;
        if ((unsigned)grow < HH) {
            const float* xb0 = x + (((size_t)b * CIN + (s / 3) * 16 + 2 * c2) * HH + grow) * WW;
            const float* xb1 = xb0 + (size_t)HH * WW;
            #pragma unroll
            for (int i = 0; i < 3; i++) {
                int j = l64 + 64 * i;
                int col = c0 - 1 + j;
                bool ok = (j < 130) && ((unsigned)col < WW);
                v0[i] = ok ? xb0[col] : 0.f;
                v1[i] = ok ? xb1[col] : 0.f;
            }
        } else {
            #pragma unroll
            for (int i = 0; i < 3; i++) { v0[i] = 0.f; v1[i] = 0.f; }
        }
    };
    auto store_X = [&](int p, const float* v0, const float* v1) {
        uint32_t* Xs = (uint32_t*)(dyn + XOFF(p));
        #pragma unroll
        for (int i = 0; i < 3; i++) {
            int j = l64 + 64 * i;
            if (j < 130) Xs[c2 * X_STRIDE + j] = packh2(v0[i], v1[i]);
        }
    };

    // ---- prologue: stage s=0 into buffer 0 ----
    {
        stage_A(0, 0);
        float v0[3], v1[3];
        load_X(0, v0, v1);
        store_X(0, v0, v1);
        asm volatile("cp.async.wait_group 0;" ::: "memory");
        __syncthreads();
    }

    // ---- main loop ----
    for (int s = 0; s < NSTAGE; s++) {
        const int p = s & 1;
        const bool pre = (s + 1 < NSTAGE);
        float v0[3], v1[3];

        if (pre) {
            stage_A(s + 1, p ^ 1);
            load_X(s + 1, v0, v1);
        }

        // ---- compute on buffer p ----
        {
            const uint4* As = (const uint4*)(dyn + AOFF(p));
            const uint32_t* Xs = (const uint32_t*)(dyn + XOFF(p));
            #pragma unroll
            for (int kc = 0; kc < 3; kc++) {
                uint32_t a[2][4];
                #pragma unroll
                for (int mm = 0; mm < 2; mm++) {
                    uint4 av = As[(kc * 8 + blk0 + mm) * 32 + lane];
                    a[mm][0] = av.x; a[mm][1] = av.y; a[mm][2] = av.z; a[mm][3] = av.w;
                }
                #pragma unroll
                for (int nn = 0; nn < 4; nn++) {
                    const uint32_t* bp = Xs + tig * X_STRIDE + pix0 + nn * 8 + g + kc;
                    uint32_t b0 = bp[0];
                    uint32_t b1 = bp[4 * X_STRIDE];
                    mma16(c[0][nn], a[0], b0, b1);
                    mma16(c[1][nn], a[1], b0, b1);
                }
            }
        }

        if (pre) store_X(p ^ 1, v0, v1);
        asm volatile("cp.async.wait_group 0;" ::: "memory");
        __syncthreads();
    }

    // ---------------- epilogue ----------------
    float bf[2][2], aw[2][2];
    #pragma unroll
    for (int mm = 0; mm < 2; mm++)
        #pragma unroll
        for (int i2 = 0; i2 < 2; i2++) {
            int ocr = oc0 + mm * 16 + g + i2 * 8;
            bf[mm][i2] = g_bfold[ocr];
            aw[mm][i2] = g_attw[ocr];
        }

    float ap_loc[4][2];
    #pragma unroll
    for (int nn = 0; nn < 4; nn++) { ap_loc[nn][0] = 0.f; ap_loc[nn][1] = 0.f; }

    #pragma unroll
    for (int mm = 0; mm < 2; mm++)
        #pragma unroll
        for (int i2 = 0; i2 < 2; i2++) {
            int ocr = oc0 + mm * 16 + g + i2 * 8;
            float* orow = out + (((size_t)b * NOC + ocr) * HH + y) * WW + c0 + pix0 + 2 * tig;
            #pragma unroll
            for (int nn = 0; nn < 4; nn++) {
                float f0 = c[mm][nn][i2 * 2 + 0] + bf[mm][i2];
                float f1 = c[mm][nn][i2 * 2 + 1] + bf[mm][i2];
                ap_loc[nn][0] = fmaf(aw[mm][i2], f0, ap_loc[nn][0]);
                ap_loc[nn][1] = fmaf(aw[mm][i2], f1, ap_loc[nn][1]);
                *(float2*)(orow + nn * 8) = make_float2(f0, f1);
            }
        }

    // reduce attention partials over g-lanes (same tig), deterministic butterfly
    #pragma unroll
    for (int nn = 0; nn < 4; nn++)
        #pragma unroll
        for (int j = 0; j < 2; j++) {
            float v = ap_loc[nn][j];
            v += __shfl_xor_sync(0xFFFFFFFF, v, 4);
            v += __shfl_xor_sync(0xFFFFFFFF, v, 8);
            v += __shfl_xor_sync(0xFFFFFFFF, v, 16);
            ap_loc[nn][j] = v;
        }
    float* att_part = (float*)dyn;   // [16 warps][32 pix] — buf0 region, free now
    if (g == 0) {
        #pragma unroll
        for (int nn = 0; nn < 4; nn++) {
            att_part[w * 32 + nn * 8 + 2 * tig + 0] = ap_loc[nn][0];
            att_part[w * 32 + nn * 8 + 2 * tig + 1] = ap_loc[nn][1];
        }
    }
    __syncthreads();

    if (tid < 256) {
        int branch = tid >> 7;       // 0: a (w_oc 0,1), 1: b (w_oc 2,3)
        int pix = tid & 127;
        int wpx = pix >> 5, pl = pix & 31;
        float ssum = att_part[((2 * branch + 0) * 4 + wpx) * 32 + pl]
                   + att_part[((2 * branch + 1) * 4 + wpx) * 32 + pl];
        int xx = c0 + pix;
        float gh = fabsf((float)y  - 127.5f) * (1.f / 128.f);
        float gw = fabsf((float)xx - 127.5f) * (1.f / 128.f);
        const float* awp = branch ? attbw : attaw;
        float pre = ssum + awp[64] * gh + awp[65] * gw + (branch ? attbb[0] : attab[0]);
        float gm = branch ? abgb[0] : abga[0];
        float bt = branch ? abbb[0] : abba[0];
        float mn = branch ? abmb[0] : abma[0];
        float vr = branch ? abvb[0] : abva[0];
        float av = (pre - mn) * gm / sqrtf(vr + 1e-5f) + bt;
        g_att[(((size_t)branch * BB + b) * HH + y) * WW + xx] = av;
    }
}

// ---------------- kernel 2: 3x3 attention conv + sigmoid + in-place gating ----------------
__global__ void __launch_bounds__(256) map_kernel(
    float* __restrict__ out,
    const float* __restrict__ wa, const float* __restrict__ wb,
    const float* __restrict__ s1, const float* __restrict__ s2)
{
    __shared__ float swa[36], swb[36];
    int t = threadIdx.y * 32 + threadIdx.x;
    if (t < 36) { swa[t] = wa[t]; swb[t] = wb[t]; }
    __syncthreads();

    int b   = blockIdx.z;
    int gy  = blockIdx.y * 8 + threadIdx.y;
    int gx4 = blockIdx.x * 128 + threadIdx.x * 4;

    const float prmax = 1.41421356237f * (127.5f / 128.f);
    const float prmin = 1.41421356237f * (0.5f / 128.f);
    const float prk = 2.f / (prmax - prmin);
    const float prc = 1.f - prmax * prk;

    float scl1 = s1[0], scl2 = s2[0];
    float mapa[4], mapb[4];
    #pragma unroll
    for (int p = 0; p < 4; p++) {
        int gx = gx4 + p;
        float sa = 0.f, sb = 0.f;
        #pragma unroll
        for (int rr = 0; rr < 3; rr++) {
            int yq = gy + rr - 1;
            if ((unsigned)yq >= HH) continue;
            #pragma unroll
            for (int ss = 0; ss < 3; ss++) {
                int xq = gx + ss - 1;
                if ((unsigned)xq >= WW) continue;
                float av = g_att[(((size_t)0 * BB + b) * HH + yq) * WW + xq];
                float bv = g_att[(((size_t)1 * BB + b) * HH + yq) * WW + xq];
                float gh = fabsf((float)yq - 127.5f) * (1.f / 128.f);
                float gw = fabsf((float)xq - 127.5f) * (1.f / 128.f);
                float pr = prk * sqrtf(gh * gh + gw * gw) + prc;
                int tap = rr * 3 + ss;
                sa += swa[tap] * av + swa[9 + tap] * gh + swa[18 + tap] * gw + swa[27 + tap] * pr;
                sb += swb[tap] * bv + swb[9 + tap] * gh + swb[18 + tap] * gw + swb[27 + tap] * pr;
            }
        }
        mapa[p] = scl1 / (1.f + expf(-sa));
        mapb[p] = scl2 / (1.f + expf(-sb));
    }

    size_t base = (((size_t)b * NOC) * HH + gy) * WW + gx4;
    #pragma unroll 4
    for (int oc = 0; oc < NOC; oc++) {
        float4 v = *(float4*)(out + base + (size_t)oc * HH * WW);
        if (oc < 64) { v.x *= mapa[0]; v.y *= mapa[1]; v.z *= mapa[2]; v.w *= mapa[3]; }
        else         { v.x *= mapb[0]; v.y *= mapb[1]; v.z *= mapb[2]; v.w *= mapb[3]; }
        *(float4*)(out + base + (size_t)oc * HH * WW) = v;
    }
}

// ---------------- launch ----------------
extern "C" void kernel_launch(void* const* d_in, const int* in_sizes, int n_in,
                              void* d_out, int out_size)
{
    const float* x     = (const float*)d_in[0];
    const float* caw   = (const float*)d_in[1];
    const float* cab   = (const float*)d_in[2];
    const float* cbw   = (const float*)d_in[3];
    const float* cbb   = (const float*)d_in[4];
    const float* bag   = (const float*)d_in[5];
    const float* babt  = (const float*)d_in[6];
    const float* bam   = (const float*)d_in[7];
    const float* bav   = (const float*)d_in[8];
    const float* bbg   = (const float*)d_in[9];
    const float* bbbt  = (const float*)d_in[10];
    const float* bbm   = (const float*)d_in[11];
    const float* bbv   = (const float*)d_in[12];
    const float* attaw = (const float*)d_in[13];
    const float* attab = (const float*)d_in[14];
    const float* attbw = (const float*)d_in[15];
    const float* attbb = (const float*)d_in[16];
    const float* abga  = (const float*)d_in[17];
    const float* abba  = (const float*)d_in[18];
    const float* abma  = (const float*)d_in[19];
    const float* abva  = (const float*)d_in[20];
    const float* abgb  = (const float*)d_in[21];
    const float* abbb  = (const float*)d_in[22];
    const float* abmb  = (const float*)d_in[23];
    const float* abvb  = (const float*)d_in[24];
    const float* anaw  = (const float*)d_in[25];
    const float* anbw  = (const float*)d_in[26];
    const float* s1    = (const float*)d_in[27];
    const float* s2    = (const float*)d_in[28];
    float* out = (float*)d_out;

    cudaFuncSetAttribute(conv_att_kernel,
                         cudaFuncAttributeMaxDynamicSharedMemorySize, DYN_BYTES);

    setup_kernel<<<(NSTAGE * A_WORDS + 255) / 256, 256>>>(
        caw, cab, cbw, cbb,
        bag, babt, bam, bav, bbg, bbbt, bbm, bbv,
        attaw, attbw);

    conv_att_kernel<<<dim3(2, HH, BB), 512, DYN_BYTES>>>(
        x, out, attaw, attab, attbw, attbb,
        abga, abba, abma, abva, abgb, abbb, abmb, abvb);

    map_kernel<<<dim3(WW / 128, HH / 8, BB), dim3(32, 8)>>>(
        out, anaw, anbw, s1, s2);
}